// round 6
// baseline (speedup 1.0000x reference)
#include <cuda_runtime.h>

// OpticalConvolution: 3x3 conv, pad 1, stride 1, NCHW fp32.
// Implicit GEMM: M=Cout=256, N=B*H*W=50176, K=Cin*9=1152.
// BM=BN=128, BK=8, 256 threads, 8x8 register tile per thread,
// double-buffered shared memory, on-the-fly im2col for the B operand.

constexpr int Cin  = 128;
constexpr int H    = 56;
constexpr int W    = 56;
constexpr int Cout = 256;
constexpr int Bsz  = 16;
constexpr int KK   = Cin * 9;        // 1152
constexpr int NPIX = H * W;          // 3136
constexpr int NTOT = Bsz * NPIX;     // 50176

constexpr int BM = 128;
constexpr int BN = 128;
constexpr int BK = 8;
constexpr int ASTRIDE = 132;         // padded to kill STS bank conflicts

__global__ __launch_bounds__(256)
void conv_igemm_kernel(const float* __restrict__ input,
                       const float* __restrict__ weights,
                       const float* __restrict__ bias,
                       float* __restrict__ out)
{
    __shared__ float As[2][BK][ASTRIDE];  // A transposed: As[k][cout_row]
    __shared__ float Bs[2][BK][BN];       // Bs[k][pixel_col]

    const int tid = threadIdx.x;
    const int tx  = tid & 15;      // 0..15 -> pixel frag
    const int ty  = tid >> 4;      // 0..15 -> cout frag
    const int n0  = blockIdx.x * BN;
    const int co0 = blockIdx.y * BM;

    // ---- A (weights) load mapping: one float4 per thread per tile ----
    const int a_row  = tid >> 1;          // 0..127 (cout row within tile)
    const int a_half = (tid & 1) * 4;     // 0 or 4 (k offset within BK)
    const float* Aptr = weights + (co0 + a_row) * KK + a_half;

    // ---- B (im2col) load mapping: 4 scalar loads per thread per tile ----
    const int krow = tid >> 5;   // 0..7   k row within tile
    const int lane = tid & 31;   // n sub-column, coalesced across warp

    // Per-thread precompute: base gmem index, spatial offset table for the
    // 9 filter taps, and a 9-bit validity mask per handled column.
    int ibase[4];
    unsigned vmask[4];
    int off9[9];
#pragma unroll
    for (int r = 0; r < 9; ++r) {
        int kh = r / 3, kw = r % 3;
        off9[r] = (kh - 1) * W + (kw - 1);
    }
#pragma unroll
    for (int j = 0; j < 4; ++j) {
        int n = n0 + lane + 32 * j;
        int b = n / NPIX;
        int s = n - b * NPIX;
        int y = s / W;
        int x = s - y * W;
        ibase[j] = b * Cin * NPIX + y * W + x;
        unsigned m = 0;
#pragma unroll
        for (int r = 0; r < 9; ++r) {
            int kh = r / 3, kw = r % 3;
            unsigned iy = (unsigned)(y + kh - 1);
            unsigned ix = (unsigned)(x + kw - 1);
            if (iy < (unsigned)H && ix < (unsigned)W) m |= (1u << r);
        }
        vmask[j] = m;
    }

    float acc[8][8];
#pragma unroll
    for (int i = 0; i < 8; ++i)
#pragma unroll
        for (int j = 0; j < 8; ++j) acc[i][j] = 0.0f;

    // Incremental k -> (cin, r) tracking for this thread's B row.
    // k = it*BK + krow advances by BK=8 each iteration.
    int cinCur = krow / 9;           // 0 for krow 0..7
    int rCur   = krow - cinCur * 9;  // = krow

    // ---- prologue: fetch tile 0 ----
    float4 aReg = *reinterpret_cast<const float4*>(Aptr);
    float  bReg[4];
    {
        int off = cinCur * NPIX + off9[rCur];
#pragma unroll
        for (int j = 0; j < 4; ++j)
            bReg[j] = (vmask[j] >> rCur) & 1u ? __ldg(input + ibase[j] + off) : 0.0f;
    }
    As[0][a_half + 0][a_row] = aReg.x;
    As[0][a_half + 1][a_row] = aReg.y;
    As[0][a_half + 2][a_row] = aReg.z;
    As[0][a_half + 3][a_row] = aReg.w;
#pragma unroll
    for (int j = 0; j < 4; ++j) Bs[0][krow][lane + 32 * j] = bReg[j];
    __syncthreads();

    const int NIT = KK / BK;  // 144
    for (int it = 0; it < NIT; ++it) {
        const int cur = it & 1;
        const int nxt = cur ^ 1;

        // ---- prefetch next tile into registers ----
        if (it + 1 < NIT) {
            const int k0n = (it + 1) * BK;
            aReg = *reinterpret_cast<const float4*>(Aptr + k0n);
            // advance (cin, r) by BK=8
            rCur += BK;
            if (rCur >= 9) { rCur -= 9; cinCur += 1; }
            int off = cinCur * NPIX + off9[rCur];
#pragma unroll
            for (int j = 0; j < 4; ++j)
                bReg[j] = (vmask[j] >> rCur) & 1u ? __ldg(input + ibase[j] + off) : 0.0f;
        }

        // ---- compute on current tile ----
#pragma unroll
        for (int kk = 0; kk < BK; ++kk) {
            float4 a0 = *reinterpret_cast<const float4*>(&As[cur][kk][ty * 4]);
            float4 a1 = *reinterpret_cast<const float4*>(&As[cur][kk][64 + ty * 4]);
            float4 b0 = *reinterpret_cast<const float4*>(&Bs[cur][kk][tx * 4]);
            float4 b1 = *reinterpret_cast<const float4*>(&Bs[cur][kk][64 + tx * 4]);
            float ar[8] = {a0.x, a0.y, a0.z, a0.w, a1.x, a1.y, a1.z, a1.w};
            float br[8] = {b0.x, b0.y, b0.z, b0.w, b1.x, b1.y, b1.z, b1.w};
#pragma unroll
            for (int i = 0; i < 8; ++i)
#pragma unroll
                for (int j = 0; j < 8; ++j)
                    acc[i][j] = fmaf(ar[i], br[j], acc[i][j]);
        }

        // ---- commit prefetch to the other buffer ----
        if (it + 1 < NIT) {
            As[nxt][a_half + 0][a_row] = aReg.x;
            As[nxt][a_half + 1][a_row] = aReg.y;
            As[nxt][a_half + 2][a_row] = aReg.z;
            As[nxt][a_half + 3][a_row] = aReg.w;
#pragma unroll
            for (int j = 0; j < 4; ++j) Bs[nxt][krow][lane + 32 * j] = bReg[j];
        }
        __syncthreads();
    }

    // ---- epilogue: add bias, store float4 (NPIX%4==0 so a 4-col group
    //      starting at a multiple of 4 never straddles a batch boundary) ----
    float bv[8];
#pragma unroll
    for (int i = 0; i < 8; ++i) {
        int row = (i < 4) ? (ty * 4 + i) : (64 + ty * 4 + (i - 4));
        bv[i] = __ldg(bias + co0 + row);
    }

#pragma unroll
    for (int jg = 0; jg < 2; ++jg) {
        int colg = jg * 64 + tx * 4;
        int n    = n0 + colg;
        int b    = n / NPIX;
        int s    = n - b * NPIX;
        float* outp = out + (size_t)b * Cout * NPIX + s;
#pragma unroll
        for (int i = 0; i < 8; ++i) {
            int row = (i < 4) ? (ty * 4 + i) : (64 + ty * 4 + (i - 4));
            int co  = co0 + row;
            float4 v;
            v.x = acc[i][jg * 4 + 0] + bv[i];
            v.y = acc[i][jg * 4 + 1] + bv[i];
            v.z = acc[i][jg * 4 + 2] + bv[i];
            v.w = acc[i][jg * 4 + 3] + bv[i];
            *reinterpret_cast<float4*>(outp + (size_t)co * NPIX) = v;
        }
    }
}

extern "C" void kernel_launch(void* const* d_in, const int* in_sizes, int n_in,
                              void* d_out, int out_size)
{
    const float* tensor  = (const float*)d_in[0];
    const float* weights = (const float*)d_in[1];
    const float* bias    = (const float*)d_in[2];
    float* out           = (float*)d_out;

    dim3 grid(NTOT / BN, Cout / BM);   // (392, 2)
    conv_igemm_kernel<<<grid, 256>>>(tensor, weights, bias, out);
}

// round 13
// speedup vs baseline: 1.6911x; 1.6911x over previous
#include <cuda_runtime.h>
#include <cuda_bf16.h>
#include <cstdint>

// ============================================================
// OpticalConvolution: 3x3 conv pad1 NCHW fp32 as implicit GEMM
//   M=Cout=256, N=B*H*W=50176, K=Cin*9=1152
// bf16 3-term split (AhiBhi + AhiBlo + AloBhi) on mma.sync
// (m16n8k16, fp32 accum). tcgen05 is unavailable: harness PTX
// target is compute_103 (non-'a'), so only family features work.
// K order: k = tap*128 + cin -> a 64-wide K chunk is one tap x
// 64 contiguous cins -> im2col gather becomes 16B cp.async.
// ============================================================

constexpr int Cin  = 128;
constexpr int H    = 56;
constexpr int W    = 56;
constexpr int Cout = 256;
constexpr int Bsz  = 16;
constexpr int NPIX = H * W;          // 3136
constexpr int NTOT = Bsz * NPIX;     // 50176
constexpr int KK   = Cin * 9;        // 1152

constexpr int BM = 128;
constexpr int BN = 128;
constexpr int KC = 64;               // K per chunk (one tap, 64 cins)
constexpr int NCHUNK = KK / KC;      // 18

// SMEM tiles: 128 rows x 64 bf16 = 128 B/row, XOR-swizzled
constexpr int TILE = BM * 128;       // 16384 B
constexpr int SMEM_TOTAL = 2 * 4 * TILE;   // 131072 B (2 bufs x {Ahi,Alo,Bhi,Blo})

// ---- device scratch ----
__device__ __align__(16) __nv_bfloat16 g_in_hi[(size_t)NTOT * Cin];
__device__ __align__(16) __nv_bfloat16 g_in_lo[(size_t)NTOT * Cin];
__device__ __align__(16) __nv_bfloat16 g_w_hi[Cout * KK];
__device__ __align__(16) __nv_bfloat16 g_w_lo[Cout * KK];

// ============================================================
// helpers
// ============================================================
__device__ __forceinline__ uint32_t smem_u32(const void* p) {
    uint32_t a;
    asm("{ .reg .u64 t; cvta.to.shared.u64 t, %1; cvt.u32.u64 %0, t; }"
        : "=r"(a) : "l"(p));
    return a;
}

__device__ __forceinline__ void cp16(uint32_t dst, const void* src, uint32_t srcsize) {
    asm volatile("cp.async.cg.shared.global [%0], [%1], 16, %2;"
                 :: "r"(dst), "l"(src), "r"(srcsize) : "memory");
}
#define CP_COMMIT() asm volatile("cp.async.commit_group;" ::: "memory")
#define CP_WAIT1()  asm volatile("cp.async.wait_group 1;" ::: "memory")
#define CP_WAIT0()  asm volatile("cp.async.wait_group 0;" ::: "memory")

#define LDSM_X4(r0, r1, r2, r3, addr) \
    asm volatile("ldmatrix.sync.aligned.m8n8.x4.shared.b16 {%0,%1,%2,%3}, [%4];" \
                 : "=r"(r0), "=r"(r1), "=r"(r2), "=r"(r3) : "r"(addr))

#define MMA_BF16(d, a, b0, b1) \
    asm volatile("mma.sync.aligned.m16n8k16.row.col.f32.bf16.bf16.f32 " \
                 "{%0,%1,%2,%3}, {%4,%5,%6,%7}, {%8,%9}, {%0,%1,%2,%3};" \
                 : "+f"((d)[0]), "+f"((d)[1]), "+f"((d)[2]), "+f"((d)[3]) \
                 : "r"((a)[0]), "r"((a)[1]), "r"((a)[2]), "r"((a)[3]), \
                   "r"(b0), "r"(b1))

// ============================================================
// Prep kernels
// ============================================================

// input: NCHW fp32 -> NHWC hi/lo bf16 (SMEM-staged transpose)
__global__ __launch_bounds__(224)
void prep_input_kernel(const float* __restrict__ in) {
    __shared__ float stage[W][33];
    const int b = blockIdx.y, y = blockIdx.x;
    const int t = threadIdx.x;           // 0..223
    const int xg = t % 56;
    const int cg = t / 56;               // 0..3
    for (int cin0 = 0; cin0 < Cin; cin0 += 32) {
#pragma unroll
        for (int j = 0; j < 8; ++j) {
            int cl = j * 4 + cg;
            stage[xg][cl] = in[((size_t)(b * Cin + cin0 + cl) * H + y) * W + xg];
        }
        __syncthreads();
#pragma unroll
        for (int j = 0; j < 8; ++j) {
            int o = t + 224 * j;          // 0..1791
            int cl = o & 31;
            int x  = o >> 5;
            float v = stage[x][cl];
            __nv_bfloat16 hi = __float2bfloat16(v);
            float lov = v - __bfloat162float(hi);
            size_t oi = ((size_t)b * NPIX + (size_t)y * W + x) * Cin + cin0 + cl;
            g_in_hi[oi] = hi;
            g_in_lo[oi] = __float2bfloat16(lov);
        }
        __syncthreads();
    }
}

// weights: [Cout][Cin][9] fp32 -> [Cout][k = tap*128 + cin] hi/lo bf16
__global__ __launch_bounds__(256)
void prep_weights_kernel(const float* __restrict__ w) {
    int o = blockIdx.x * 256 + threadIdx.x;
    if (o >= Cout * KK) return;
    int cout = o / KK;
    int k    = o - cout * KK;
    int r    = k >> 7;           // tap 0..8
    int cin  = k & 127;
    float v = w[((size_t)cout * Cin + cin) * 9 + r];
    __nv_bfloat16 hi = __float2bfloat16(v);
    g_w_hi[o] = hi;
    g_w_lo[o] = __float2bfloat16(v - __bfloat162float(hi));
}

// ============================================================
// Main mma.sync kernel
// ============================================================
__global__ __launch_bounds__(256, 1)
void conv_mma_kernel(const float* __restrict__ bias, float* __restrict__ out) {
    extern __shared__ char smem[];
    const uint32_t sb = smem_u32(smem);
    const int tid = threadIdx.x;
    const int wid = tid >> 5;
    const int lid = tid & 31;
    const int warpM = wid >> 2;       // 0..1  -> 64 cout rows
    const int warpN = wid & 3;        // 0..3  -> 32 pixel cols

    const int n0  = blockIdx.x * BN;
    const int co0 = blockIdx.y * BM;

    // ---- load mapping: 2 threads per tile-row; parity = hi/lo term ----
    const int lrow  = tid >> 1;       // 0..127
    const int lterm = tid & 1;        // 0 = hi, 1 = lo
    const uint32_t lsw = (uint32_t)(lrow & 7) * 16;   // swizzle for stores

    const int n  = n0 + lrow;
    const int bb = n / NPIX;
    const int s  = n - bb * NPIX;
    const int py = s / W;
    const int px = s - py * W;
    const size_t pixBase = ((size_t)bb * NPIX + (size_t)py * W + px) * Cin;
    const __nv_bfloat16* binSrc = lterm ? g_in_lo : g_in_hi;
    const __nv_bfloat16* winSrc = lterm ? g_w_lo : g_w_hi;
    const size_t wBase = (size_t)(co0 + lrow) * KK;

    // ---- per-lane ldmatrix constants ----
    const uint32_t aRowSel = (uint32_t)(lid & 15);
    const uint32_t aK16    = (uint32_t)(lid >> 4) * 16;
    const uint32_t swA     = (aRowSel & 7) * 16;
    const uint32_t bRowSel = (uint32_t)((lid & 7) + ((lid >> 4) & 1) * 8);
    const uint32_t bK16    = (uint32_t)((lid >> 3) & 1) * 16;
    const uint32_t swB     = (bRowSel & 7) * 16;

    float acc[4][4][4];
#pragma unroll
    for (int i = 0; i < 4; ++i)
#pragma unroll
        for (int j = 0; j < 4; ++j)
#pragma unroll
            for (int q = 0; q < 4; ++q) acc[i][j][q] = 0.0f;

    // ---- chunk load (cp.async, zero-fill for invalid taps) ----
    auto issue = [&](int c) {
        const int buf = c & 1;
        const uint32_t base = sb + (uint32_t)buf * (4 * TILE);
        const uint32_t aT = base + (uint32_t)lterm * TILE;
        const uint32_t bT = base + 2 * TILE + (uint32_t)lterm * TILE;
        const int r    = c >> 1;
        const int cin0 = (c & 1) * 64;
        const int dy   = r / 3 - 1;
        const int dx   = r - (r / 3) * 3 - 1;

        const __nv_bfloat16* asrc = winSrc + wBase + (size_t)c * KC;
        const uint32_t aRowAddr = aT + (uint32_t)lrow * 128;
#pragma unroll
        for (int j = 0; j < 8; ++j)
            cp16(aRowAddr + (((uint32_t)j * 16) ^ lsw), asrc + j * 8, 16);

        const bool valid = ((unsigned)(py + dy) < (unsigned)H) &&
                           ((unsigned)(px + dx) < (unsigned)W);
        const __nv_bfloat16* bsrc = valid
            ? binSrc + pixBase + (ptrdiff_t)(dy * W + dx) * Cin + cin0
            : binSrc + pixBase;                    // safe addr; 0 bytes read
        const uint32_t ssz = valid ? 16u : 0u;
        const uint32_t bRowAddr = bT + (uint32_t)lrow * 128;
#pragma unroll
        for (int j = 0; j < 8; ++j)
            cp16(bRowAddr + (((uint32_t)j * 16) ^ lsw), bsrc + j * 8, ssz);
    };

    issue(0);
    CP_COMMIT();

    for (int c = 0; c < NCHUNK; ++c) {
        if (c + 1 < NCHUNK) { issue(c + 1); CP_COMMIT(); CP_WAIT1(); }
        else                { CP_WAIT0(); }
        __syncthreads();

        const uint32_t base = sb + (uint32_t)(c & 1) * (4 * TILE);
#pragma unroll
        for (int t = 0; t < 3; ++t) {       // 0: hh, 1: h*lo(B), 2: lo(A)*h
            const uint32_t aB = base + (t == 2 ? TILE : 0);
            const uint32_t bB = base + 2 * TILE + (t == 1 ? TILE : 0);
#pragma unroll
            for (int ks = 0; ks < 4; ++ks) {
                uint32_t a[4][4];
#pragma unroll
                for (int mf = 0; mf < 4; ++mf) {
                    uint32_t addr = aB
                        + (uint32_t)(warpM * 64 + mf * 16 + aRowSel) * 128
                        + (((uint32_t)ks * 32 + aK16) ^ swA);
                    LDSM_X4(a[mf][0], a[mf][1], a[mf][2], a[mf][3], addr);
                }
                uint32_t b[2][4];
#pragma unroll
                for (int np = 0; np < 2; ++np) {
                    uint32_t addr = bB
                        + (uint32_t)(warpN * 32 + np * 16 + bRowSel) * 128
                        + (((uint32_t)ks * 32 + bK16) ^ swB);
                    LDSM_X4(b[np][0], b[np][1], b[np][2], b[np][3], addr);
                }
#pragma unroll
                for (int mf = 0; mf < 4; ++mf)
#pragma unroll
                    for (int nf = 0; nf < 4; ++nf)
                        MMA_BF16(acc[mf][nf], a[mf],
                                 b[nf >> 1][(nf & 1) * 2],
                                 b[nf >> 1][(nf & 1) * 2 + 1]);
            }
        }
        __syncthreads();
    }

    // ---- epilogue: bias + float2 stores ----
    // m16n8 D frag: lane l -> rows (l>>2) and (l>>2)+8; cols (l&3)*2 + {0,1}
    const int rQuad = lid >> 2;
    const int cPair = (lid & 3) * 2;
#pragma unroll
    for (int mf = 0; mf < 4; ++mf) {
        const int coA = co0 + warpM * 64 + mf * 16 + rQuad;
        const int coB = coA + 8;
        const float bvA = __ldg(bias + coA);
        const float bvB = __ldg(bias + coB);
#pragma unroll
        for (int nf = 0; nf < 4; ++nf) {
            const int nn = n0 + warpN * 32 + nf * 8 + cPair;
            const int b2 = nn / NPIX;
            const int s2 = nn - b2 * NPIX;      // even; NPIX even -> no straddle
            float* po = out + ((size_t)b2 * Cout) * NPIX + s2;
            float2 vA, vB;
            vA.x = acc[mf][nf][0] + bvA;
            vA.y = acc[mf][nf][1] + bvA;
            vB.x = acc[mf][nf][2] + bvB;
            vB.y = acc[mf][nf][3] + bvB;
            *reinterpret_cast<float2*>(po + (size_t)coA * NPIX) = vA;
            *reinterpret_cast<float2*>(po + (size_t)coB * NPIX) = vB;
        }
    }
}

// ============================================================
// launch
// ============================================================
extern "C" void kernel_launch(void* const* d_in, const int* in_sizes, int n_in,
                              void* d_out, int out_size) {
    const float* tensor  = (const float*)d_in[0];
    const float* weights = (const float*)d_in[1];
    const float* bias    = (const float*)d_in[2];
    float* out           = (float*)d_out;

    prep_input_kernel<<<dim3(H, Bsz), 224>>>(tensor);
    prep_weights_kernel<<<(Cout * KK + 255) / 256, 256>>>(weights);

    cudaFuncSetAttribute(conv_mma_kernel,
                         cudaFuncAttributeMaxDynamicSharedMemorySize, SMEM_TOTAL);
    conv_mma_kernel<<<dim3(NTOT / BN, Cout / BM), 256, SMEM_TOTAL>>>(bias, out);
}